// round 12
// baseline (speedup 1.0000x reference)
#include <cuda_runtime.h>
#include <cstdint>

#define N_VERTS 262144
#define N_PAIRS 8388608
#define DHAT2 0.0025f
#define EPSF 1e-12f

#define MAIN_BLOCK 256
#define MAIN_GRID 2048
// n4 = N_PAIRS/4 = 2097152 = 4 * (MAIN_GRID*MAIN_BLOCK) exactly -> 16 pairs/thread.

// Scratch: current coordinates (rest + displacement), fits in L2 (2 MB).
__device__ float2 g_coords[N_VERTS];

// ---------------------------------------------------------------------------
// Kernel A: coords = rest + Uu.reshape(-1,2); zero the output scalar.
// __stcg: write straight toward L2 (no L1 fill) so the table is L2-resident
// when kernel B's gathers begin. Early PDL trigger releases B's launch.
// ---------------------------------------------------------------------------
__global__ void __launch_bounds__(512)
build_coords_kernel(const float4* __restrict__ Uu,
                    const float4* __restrict__ rest,
                    float* __restrict__ out) {
    int i = blockIdx.x * blockDim.x + threadIdx.x;  // indexes vert pairs
    if (i < N_VERTS / 2) {
        float4 r = __ldg(&rest[i]);
        float4 u = __ldg(&Uu[i]);
        float4 c = make_float4(r.x + u.x, r.y + u.y, r.z + u.z, r.w + u.w);
        __stcg(reinterpret_cast<float4*>(g_coords) + i, c);
    }
    if (blockIdx.x == 0 && threadIdx.x == 0) {
        out[0] = 0.0f;  // d_out is poisoned; initialize
    }
    cudaTriggerProgrammaticLaunchCompletion();
}

// ---------------------------------------------------------------------------
// Per-pair barrier term (reference math, fp32; fast log/div — rel tolerance
// is 1e-3, __logf error ~5e-7).
// ---------------------------------------------------------------------------
__device__ __forceinline__ float pair_barrier(int iv, int ie0, int ie1) {
    float2 p = __ldg(&g_coords[iv]);
    float2 a = __ldg(&g_coords[ie0]);
    float2 b = __ldg(&g_coords[ie1]);

    float abx = b.x - a.x, aby = b.y - a.y;
    float apx = p.x - a.x, apy = p.y - a.y;
    float denom = abx * abx + aby * aby;
    float t = __fdividef(apx * abx + apy * aby, fmaxf(denom, EPSF));
    t = fminf(fmaxf(t, 0.0f), 1.0f);
    float dx = apx - t * abx;
    float dy = apy - t * aby;
    float d2 = dx * dx + dy * dy;

    if (d2 < DHAT2) {
        float d2s = fmaxf(d2, EPSF);
        float m = d2s - DHAT2;
        return -(m * m) * __logf(d2s * (1.0f / DHAT2));
    }
    return 0.0f;
}

__device__ __forceinline__ float group_barrier(int4 v, int4 e0, int4 e1) {
    return pair_barrier(v.x, e0.x, e1.x)
         + pair_barrier(v.y, e0.y, e1.y)
         + pair_barrier(v.z, e0.z, e1.z)
         + pair_barrier(v.w, e0.w, e1.w);
}

// ---------------------------------------------------------------------------
// Kernel B (champion R7/R10 shape): PDL secondary. Streaming index prefetch
// of all 12 int4 vectors while kernel A runs, grid-dependency sync, then
// per-group compiler-interleaved gather+compute. 44 regs, L1tex-saturated.
// ---------------------------------------------------------------------------
__global__ void __launch_bounds__(MAIN_BLOCK)
barrier_energy_kernel(const int4* __restrict__ pv4,
                      const int4* __restrict__ pe04,
                      const int4* __restrict__ pe14,
                      float* __restrict__ out) {
    const int S = MAIN_GRID * MAIN_BLOCK;  // 524288
    int tid = blockIdx.x * MAIN_BLOCK + threadIdx.x;

    // Phase 1: coalesced streaming index prefetch — independent of kernel A.
    int4 v0  = __ldcs(&pv4[tid]);
    int4 e00 = __ldcs(&pe04[tid]);
    int4 e10 = __ldcs(&pe14[tid]);
    int4 v1  = __ldcs(&pv4[tid + S]);
    int4 e01 = __ldcs(&pe04[tid + S]);
    int4 e11 = __ldcs(&pe14[tid + S]);
    int4 v2  = __ldcs(&pv4[tid + 2 * S]);
    int4 e02 = __ldcs(&pe04[tid + 2 * S]);
    int4 e12 = __ldcs(&pe14[tid + 2 * S]);
    int4 v3  = __ldcs(&pv4[tid + 3 * S]);
    int4 e03 = __ldcs(&pe04[tid + 3 * S]);
    int4 e13 = __ldcs(&pe14[tid + 3 * S]);

    // Wait for kernel A (g_coords) to be complete and visible.
    cudaGridDependencySynchronize();

    float s0 = group_barrier(v0, e00, e10);
    float s1 = group_barrier(v1, e01, e11);
    float s2 = group_barrier(v2, e02, e12);
    float s3 = group_barrier(v3, e03, e13);
    double acc = (double)(s0 + s1) + (double)(s2 + s3);

    // Warp reduction
    #pragma unroll
    for (int off = 16; off > 0; off >>= 1)
        acc += __shfl_xor_sync(0xFFFFFFFFu, acc, off);

    __shared__ double warp_sums[MAIN_BLOCK / 32];
    int lane = threadIdx.x & 31;
    int wid = threadIdx.x >> 5;
    if (lane == 0) warp_sums[wid] = acc;
    __syncthreads();

    if (wid == 0) {
        double vsum = (lane < (MAIN_BLOCK / 32)) ? warp_sums[lane] : 0.0;
        #pragma unroll
        for (int off = 4; off > 0; off >>= 1)
            vsum += __shfl_xor_sync(0xFFFFFFFFu, vsum, off);
        if (lane == 0)
            atomicAdd(out, (float)vsum);
    }
}

// ---------------------------------------------------------------------------
extern "C" void kernel_launch(void* const* d_in, const int* in_sizes, int n_in,
                              void* d_out, int out_size) {
    const float4* Uu   = (const float4*)d_in[0];
    const float4* rest = (const float4*)d_in[1];
    const int4* pv  = (const int4*)d_in[2];
    const int4* pe0 = (const int4*)d_in[3];
    const int4* pe1 = (const int4*)d_in[4];
    float* out = (float*)d_out;

    // Kernel A (contains the early programmatic-completion trigger).
    {
        cudaLaunchConfig_t acfg = {};
        acfg.gridDim = dim3(256, 1, 1);      // 256 * 512 = 131072 = N_VERTS/2
        acfg.blockDim = dim3(512, 1, 1);
        acfg.dynamicSmemBytes = 0;
        acfg.stream = 0;
        acfg.attrs = nullptr;
        acfg.numAttrs = 0;
        cudaLaunchKernelEx(&acfg, build_coords_kernel, Uu, rest, out);
    }

    // PDL launch: B starts while A runs; B blocks at
    // cudaGridDependencySynchronize() until A completes.
    cudaLaunchAttribute attrs[1];
    attrs[0].id = cudaLaunchAttributeProgrammaticStreamSerialization;
    attrs[0].val.programmaticStreamSerializationAllowed = 1;

    cudaLaunchConfig_t cfg = {};
    cfg.gridDim = dim3(MAIN_GRID, 1, 1);
    cfg.blockDim = dim3(MAIN_BLOCK, 1, 1);
    cfg.dynamicSmemBytes = 0;
    cfg.stream = 0;
    cfg.attrs = attrs;
    cfg.numAttrs = 1;

    cudaLaunchKernelEx(&cfg, barrier_energy_kernel, pv, pe0, pe1, out);
}

// round 13
// speedup vs baseline: 1.0117x; 1.0117x over previous
#include <cuda_runtime.h>
#include <cstdint>

#define N_VERTS 262144
#define N_PAIRS 8388608
#define DHAT2 0.0025f
#define EPSF 1e-12f

#define MAIN_BLOCK 256
#define MAIN_GRID 2048
// n4 = N_PAIRS/4 = 2097152 = 4 * (MAIN_GRID*MAIN_BLOCK) exactly -> 16 pairs/thread.

// Scratch: current coordinates (rest + displacement), fits in L2 (2 MB).
__device__ float2 g_coords[N_VERTS];

// ---------------------------------------------------------------------------
// Kernel A: coords = rest + Uu.reshape(-1,2); zero the output scalar.
// Early PDL trigger releases kernel B's launch as soon as stores are issued
// (visibility is still enforced by B's cudaGridDependencySynchronize).
// ---------------------------------------------------------------------------
__global__ void __launch_bounds__(512)
build_coords_kernel(const float4* __restrict__ Uu,
                    const float4* __restrict__ rest,
                    float* __restrict__ out) {
    int i = blockIdx.x * blockDim.x + threadIdx.x;  // indexes vert pairs
    if (i < N_VERTS / 2) {
        float4 r = __ldg(&rest[i]);
        float4 u = __ldg(&Uu[i]);
        float4 c = make_float4(r.x + u.x, r.y + u.y, r.z + u.z, r.w + u.w);
        reinterpret_cast<float4*>(g_coords)[i] = c;
    }
    if (blockIdx.x == 0 && threadIdx.x == 0) {
        out[0] = 0.0f;  // d_out is poisoned; initialize
    }
    cudaTriggerProgrammaticLaunchCompletion();
}

// ---------------------------------------------------------------------------
// Per-pair barrier term (reference math, fp32; fast log/div — rel tolerance
// is 1e-3, __logf error ~5e-7).
// ---------------------------------------------------------------------------
__device__ __forceinline__ float pair_barrier(int iv, int ie0, int ie1) {
    float2 p = __ldg(&g_coords[iv]);
    float2 a = __ldg(&g_coords[ie0]);
    float2 b = __ldg(&g_coords[ie1]);

    float abx = b.x - a.x, aby = b.y - a.y;
    float apx = p.x - a.x, apy = p.y - a.y;
    float denom = abx * abx + aby * aby;
    float t = __fdividef(apx * abx + apy * aby, fmaxf(denom, EPSF));
    t = fminf(fmaxf(t, 0.0f), 1.0f);
    float dx = apx - t * abx;
    float dy = apy - t * aby;
    float d2 = dx * dx + dy * dy;

    if (d2 < DHAT2) {
        float d2s = fmaxf(d2, EPSF);
        float m = d2s - DHAT2;
        return -(m * m) * __logf(d2s * (1.0f / DHAT2));
    }
    return 0.0f;
}

__device__ __forceinline__ float group_barrier(int4 v, int4 e0, int4 e1) {
    return pair_barrier(v.x, e0.x, e1.x)
         + pair_barrier(v.y, e0.y, e1.y)
         + pair_barrier(v.z, e0.z, e1.z)
         + pair_barrier(v.w, e0.w, e1.w);
}

// ---------------------------------------------------------------------------
// Kernel B (champion R7/R10 shape): PDL secondary. Streaming index prefetch
// of all 12 int4 vectors while kernel A runs, grid-dependency sync, then
// per-group compiler-interleaved gather+compute. 44 regs, L1tex-saturated
// (~97% of the sm_103a random-gather wavefront floor).
// ---------------------------------------------------------------------------
__global__ void __launch_bounds__(MAIN_BLOCK)
barrier_energy_kernel(const int4* __restrict__ pv4,
                      const int4* __restrict__ pe04,
                      const int4* __restrict__ pe14,
                      float* __restrict__ out) {
    const int S = MAIN_GRID * MAIN_BLOCK;  // 524288
    int tid = blockIdx.x * MAIN_BLOCK + threadIdx.x;

    // Phase 1: coalesced streaming index prefetch — independent of kernel A.
    int4 v0  = __ldcs(&pv4[tid]);
    int4 e00 = __ldcs(&pe04[tid]);
    int4 e10 = __ldcs(&pe14[tid]);
    int4 v1  = __ldcs(&pv4[tid + S]);
    int4 e01 = __ldcs(&pe04[tid + S]);
    int4 e11 = __ldcs(&pe14[tid + S]);
    int4 v2  = __ldcs(&pv4[tid + 2 * S]);
    int4 e02 = __ldcs(&pe04[tid + 2 * S]);
    int4 e12 = __ldcs(&pe14[tid + 2 * S]);
    int4 v3  = __ldcs(&pv4[tid + 3 * S]);
    int4 e03 = __ldcs(&pe04[tid + 3 * S]);
    int4 e13 = __ldcs(&pe14[tid + 3 * S]);

    // Wait for kernel A (g_coords) to be complete and visible.
    cudaGridDependencySynchronize();

    float s0 = group_barrier(v0, e00, e10);
    float s1 = group_barrier(v1, e01, e11);
    float s2 = group_barrier(v2, e02, e12);
    float s3 = group_barrier(v3, e03, e13);
    double acc = (double)(s0 + s1) + (double)(s2 + s3);

    // Warp reduction
    #pragma unroll
    for (int off = 16; off > 0; off >>= 1)
        acc += __shfl_xor_sync(0xFFFFFFFFu, acc, off);

    __shared__ double warp_sums[MAIN_BLOCK / 32];
    int lane = threadIdx.x & 31;
    int wid = threadIdx.x >> 5;
    if (lane == 0) warp_sums[wid] = acc;
    __syncthreads();

    if (wid == 0) {
        double vsum = (lane < (MAIN_BLOCK / 32)) ? warp_sums[lane] : 0.0;
        #pragma unroll
        for (int off = 4; off > 0; off >>= 1)
            vsum += __shfl_xor_sync(0xFFFFFFFFu, vsum, off);
        if (lane == 0)
            atomicAdd(out, (float)vsum);
    }
}

// ---------------------------------------------------------------------------
extern "C" void kernel_launch(void* const* d_in, const int* in_sizes, int n_in,
                              void* d_out, int out_size) {
    const float4* Uu   = (const float4*)d_in[0];
    const float4* rest = (const float4*)d_in[1];
    const int4* pv  = (const int4*)d_in[2];
    const int4* pe0 = (const int4*)d_in[3];
    const int4* pe1 = (const int4*)d_in[4];
    float* out = (float*)d_out;

    // Kernel A (contains the early programmatic-completion trigger).
    {
        cudaLaunchConfig_t acfg = {};
        acfg.gridDim = dim3(256, 1, 1);      // 256 * 512 = 131072 = N_VERTS/2
        acfg.blockDim = dim3(512, 1, 1);
        acfg.dynamicSmemBytes = 0;
        acfg.stream = 0;
        acfg.attrs = nullptr;
        acfg.numAttrs = 0;
        cudaLaunchKernelEx(&acfg, build_coords_kernel, Uu, rest, out);
    }

    // PDL launch: B starts while A runs; B blocks at
    // cudaGridDependencySynchronize() until A completes.
    cudaLaunchAttribute attrs[1];
    attrs[0].id = cudaLaunchAttributeProgrammaticStreamSerialization;
    attrs[0].val.programmaticStreamSerializationAllowed = 1;

    cudaLaunchConfig_t cfg = {};
    cfg.gridDim = dim3(MAIN_GRID, 1, 1);
    cfg.blockDim = dim3(MAIN_BLOCK, 1, 1);
    cfg.dynamicSmemBytes = 0;
    cfg.stream = 0;
    cfg.attrs = attrs;
    cfg.numAttrs = 1;

    cudaLaunchKernelEx(&cfg, barrier_energy_kernel, pv, pe0, pe1, out);
}

// round 14
// speedup vs baseline: 1.0120x; 1.0004x over previous
#include <cuda_runtime.h>
#include <cstdint>

#define N_VERTS 262144
#define N_PAIRS 8388608
#define DHAT2 0.0025f
#define EPSF 1e-12f

#define MAIN_BLOCK 256
#define MAIN_GRID 2048
// n4 = N_PAIRS/4 = 2097152 = 4 * (MAIN_GRID*MAIN_BLOCK) exactly -> 16 pairs/thread.

// Scratch: current coordinates (rest + displacement), fits in L2 (2 MB).
__device__ float2 g_coords[N_VERTS];

// ---------------------------------------------------------------------------
// Kernel A: coords = rest + Uu.reshape(-1,2); zero the output scalar.
// 128 blocks x 1024 threads, one float4 (2 verts) per thread, exact cover.
// Early PDL trigger releases kernel B's launch as soon as stores are issued
// (visibility is still enforced by B's cudaGridDependencySynchronize).
// ---------------------------------------------------------------------------
__global__ void __launch_bounds__(1024)
build_coords_kernel(const float4* __restrict__ Uu,
                    const float4* __restrict__ rest,
                    float* __restrict__ out) {
    int i = blockIdx.x * blockDim.x + threadIdx.x;  // indexes vert pairs
    if (i < N_VERTS / 2) {
        float4 r = __ldg(&rest[i]);
        float4 u = __ldg(&Uu[i]);
        float4 c = make_float4(r.x + u.x, r.y + u.y, r.z + u.z, r.w + u.w);
        reinterpret_cast<float4*>(g_coords)[i] = c;
    }
    if (blockIdx.x == 0 && threadIdx.x == 0) {
        out[0] = 0.0f;  // d_out is poisoned; initialize
    }
    cudaTriggerProgrammaticLaunchCompletion();
}

// ---------------------------------------------------------------------------
// Per-pair barrier term (reference math, fp32; fast log/div — rel tolerance
// is 1e-3, __logf error ~5e-7).
// ---------------------------------------------------------------------------
__device__ __forceinline__ float pair_barrier(int iv, int ie0, int ie1) {
    float2 p = __ldg(&g_coords[iv]);
    float2 a = __ldg(&g_coords[ie0]);
    float2 b = __ldg(&g_coords[ie1]);

    float abx = b.x - a.x, aby = b.y - a.y;
    float apx = p.x - a.x, apy = p.y - a.y;
    float denom = abx * abx + aby * aby;
    float t = __fdividef(apx * abx + apy * aby, fmaxf(denom, EPSF));
    t = fminf(fmaxf(t, 0.0f), 1.0f);
    float dx = apx - t * abx;
    float dy = apy - t * aby;
    float d2 = dx * dx + dy * dy;

    if (d2 < DHAT2) {
        float d2s = fmaxf(d2, EPSF);
        float m = d2s - DHAT2;
        return -(m * m) * __logf(d2s * (1.0f / DHAT2));
    }
    return 0.0f;
}

__device__ __forceinline__ float group_barrier(int4 v, int4 e0, int4 e1) {
    return pair_barrier(v.x, e0.x, e1.x)
         + pair_barrier(v.y, e0.y, e1.y)
         + pair_barrier(v.z, e0.z, e1.z)
         + pair_barrier(v.w, e0.w, e1.w);
}

// ---------------------------------------------------------------------------
// Kernel B (champion shape): PDL secondary. Streaming index prefetch of all
// 12 int4 vectors while kernel A runs, grid-dependency sync, then per-group
// compiler-interleaved gather+compute. 44 regs, L1tex-saturated (~97% of the
// sm_103a random-gather wavefront floor).
// ---------------------------------------------------------------------------
__global__ void __launch_bounds__(MAIN_BLOCK)
barrier_energy_kernel(const int4* __restrict__ pv4,
                      const int4* __restrict__ pe04,
                      const int4* __restrict__ pe14,
                      float* __restrict__ out) {
    const int S = MAIN_GRID * MAIN_BLOCK;  // 524288
    int tid = blockIdx.x * MAIN_BLOCK + threadIdx.x;

    // Phase 1: coalesced streaming index prefetch — independent of kernel A.
    int4 v0  = __ldcs(&pv4[tid]);
    int4 e00 = __ldcs(&pe04[tid]);
    int4 e10 = __ldcs(&pe14[tid]);
    int4 v1  = __ldcs(&pv4[tid + S]);
    int4 e01 = __ldcs(&pe04[tid + S]);
    int4 e11 = __ldcs(&pe14[tid + S]);
    int4 v2  = __ldcs(&pv4[tid + 2 * S]);
    int4 e02 = __ldcs(&pe04[tid + 2 * S]);
    int4 e12 = __ldcs(&pe14[tid + 2 * S]);
    int4 v3  = __ldcs(&pv4[tid + 3 * S]);
    int4 e03 = __ldcs(&pe04[tid + 3 * S]);
    int4 e13 = __ldcs(&pe14[tid + 3 * S]);

    // Wait for kernel A (g_coords) to be complete and visible.
    cudaGridDependencySynchronize();

    float s0 = group_barrier(v0, e00, e10);
    float s1 = group_barrier(v1, e01, e11);
    float s2 = group_barrier(v2, e02, e12);
    float s3 = group_barrier(v3, e03, e13);
    double acc = (double)(s0 + s1) + (double)(s2 + s3);

    // Warp reduction
    #pragma unroll
    for (int off = 16; off > 0; off >>= 1)
        acc += __shfl_xor_sync(0xFFFFFFFFu, acc, off);

    __shared__ double warp_sums[MAIN_BLOCK / 32];
    int lane = threadIdx.x & 31;
    int wid = threadIdx.x >> 5;
    if (lane == 0) warp_sums[wid] = acc;
    __syncthreads();

    if (wid == 0) {
        double vsum = (lane < (MAIN_BLOCK / 32)) ? warp_sums[lane] : 0.0;
        #pragma unroll
        for (int off = 4; off > 0; off >>= 1)
            vsum += __shfl_xor_sync(0xFFFFFFFFu, vsum, off);
        if (lane == 0)
            atomicAdd(out, (float)vsum);
    }
}

// ---------------------------------------------------------------------------
extern "C" void kernel_launch(void* const* d_in, const int* in_sizes, int n_in,
                              void* d_out, int out_size) {
    const float4* Uu   = (const float4*)d_in[0];
    const float4* rest = (const float4*)d_in[1];
    const int4* pv  = (const int4*)d_in[2];
    const int4* pe0 = (const int4*)d_in[3];
    const int4* pe1 = (const int4*)d_in[4];
    float* out = (float*)d_out;

    // Kernel A (contains the early programmatic-completion trigger).
    {
        cudaLaunchConfig_t acfg = {};
        acfg.gridDim = dim3(128, 1, 1);      // 128 * 1024 = 131072 = N_VERTS/2
        acfg.blockDim = dim3(1024, 1, 1);
        acfg.dynamicSmemBytes = 0;
        acfg.stream = 0;
        acfg.attrs = nullptr;
        acfg.numAttrs = 0;
        cudaLaunchKernelEx(&acfg, build_coords_kernel, Uu, rest, out);
    }

    // PDL launch: B starts while A runs; B blocks at
    // cudaGridDependencySynchronize() until A completes.
    cudaLaunchAttribute attrs[1];
    attrs[0].id = cudaLaunchAttributeProgrammaticStreamSerialization;
    attrs[0].val.programmaticStreamSerializationAllowed = 1;

    cudaLaunchConfig_t cfg = {};
    cfg.gridDim = dim3(MAIN_GRID, 1, 1);
    cfg.blockDim = dim3(MAIN_BLOCK, 1, 1);
    cfg.dynamicSmemBytes = 0;
    cfg.stream = 0;
    cfg.attrs = attrs;
    cfg.numAttrs = 1;

    cudaLaunchKernelEx(&cfg, barrier_energy_kernel, pv, pe0, pe1, out);
}